// round 8
// baseline (speedup 1.0000x reference)
#include <cuda_runtime.h>
#include <cstdint>
#include <cfloat>

// Problem constants (fixed by the reference)
#define NB   8192
#define EMB  768
#define NP   96
#define NK   256
#define ND   8
#define NKP  (NK / 2)        // 128 k-pair steps

#define NCHUNK 16            // chunks of 8 pair-steps = 16 codes
#define SPC    8             // pair-steps per chunk

#define THREADS      128
#define ROWS_PER_T   4
#define ROWS_PER_BLK (THREADS * ROWS_PER_T)   // 512
#define GRID_X       (NB / ROWS_PER_BLK)      // 16

#define PAIR_STRIDE  10      // u64 per k-pair record (8 dims + c2 + pad)

typedef unsigned long long u64;

__device__ __forceinline__ u64 ffma2(u64 a, u64 b, u64 c) {
    u64 d;
    asm("fma.rn.f32x2 %0, %1, %2, %3;" : "=l"(d) : "l"(a), "l"(b), "l"(c));
    return d;
}
__device__ __forceinline__ u64 pack2(float lo, float hi) {
    u64 r;
    asm("mov.b64 %0, {%1, %2};" : "=l"(r) : "f"(lo), "f"(hi));
    return r;
}
__device__ __forceinline__ void unpack2(u64 v, float& lo, float& hi) {
    asm("mov.b64 {%0, %1}, %2;" : "=f"(lo), "=f"(hi) : "l"(v));
}

// Exact score chain — serially dependent, so recomputation is bit-identical.
__device__ __forceinline__ u64 score_pair(u64 c2, ulonglong2 q0, ulonglong2 q1,
                                          ulonglong2 q2, ulonglong2 q3,
                                          const u64* vd) {
    u64 acc = c2;
    acc = ffma2(vd[0], q0.x, acc);
    acc = ffma2(vd[1], q0.y, acc);
    acc = ffma2(vd[2], q1.x, acc);
    acc = ffma2(vd[3], q1.y, acc);
    acc = ffma2(vd[4], q2.x, acc);
    acc = ffma2(vd[5], q2.y, acc);
    acc = ffma2(vd[6], q3.x, acc);
    acc = ffma2(vd[7], q3.y, acc);
    return acc;
}

__global__ __launch_bounds__(THREADS, 5)
void pq_argmin_kernel(const float* __restrict__ vecs,
                      const float* __restrict__ codebook,
                      float* __restrict__ out) {
    // Per k-pair record: d0..d7 packed as (-2*c_{2s,d}, -2*c_{2s+1,d}),
    // then (||c_2s||^2, ||c_2s+1||^2). Stride 10 u64 = 80B.
    __shared__ __align__(16) u64 s_pair[NKP][PAIR_STRIDE];  // 10 KB

    const int p   = blockIdx.y;
    const int tid = threadIdx.x;

    // ---- stage codebook[p] into smem: one k-pair per thread ----
    {
        const int kp = tid;  // THREADS == NKP
        const float4* cb = reinterpret_cast<const float4*>(
            codebook + ((size_t)p * NK + 2 * kp) * ND);
        float4 a0 = cb[0], a1 = cb[1];   // code 2kp
        float4 b0 = cb[2], b1 = cb[3];   // code 2kp+1
        float c2a = a0.x*a0.x + a0.y*a0.y + a0.z*a0.z + a0.w*a0.w
                  + a1.x*a1.x + a1.y*a1.y + a1.z*a1.z + a1.w*a1.w;
        float c2b = b0.x*b0.x + b0.y*b0.y + b0.z*b0.z + b0.w*b0.w
                  + b1.x*b1.x + b1.y*b1.y + b1.z*b1.z + b1.w*b1.w;
        u64* rec = s_pair[kp];
        rec[0] = pack2(-2.f*a0.x, -2.f*b0.x);
        rec[1] = pack2(-2.f*a0.y, -2.f*b0.y);
        rec[2] = pack2(-2.f*a0.z, -2.f*b0.z);
        rec[3] = pack2(-2.f*a0.w, -2.f*b0.w);
        rec[4] = pack2(-2.f*a1.x, -2.f*b1.x);
        rec[5] = pack2(-2.f*a1.y, -2.f*b1.y);
        rec[6] = pack2(-2.f*a1.z, -2.f*b1.z);
        rec[7] = pack2(-2.f*a1.w, -2.f*b1.w);
        rec[8] = pack2(c2a, c2b);
    }
    __syncthreads();

    // ---- load 4 rows' v-slices (each slice is one 32B sector) ----
    const int rowBase = blockIdx.x * ROWS_PER_BLK;
    int rows[ROWS_PER_T];
    rows[0] = rowBase + tid;
    rows[1] = rows[0] + THREADS;
    rows[2] = rows[0] + 2 * THREADS;
    rows[3] = rows[0] + 3 * THREADS;

    // v duplicated into both f32x2 lanes, per row per dim.
    // vd is only ever indexed by compile-time constants.
    u64 vd[ROWS_PER_T][ND];
#pragma unroll
    for (int r = 0; r < ROWS_PER_T; r++) {
        const float4* g = reinterpret_cast<const float4*>(
            vecs + (size_t)rows[r] * EMB + p * ND);
        float4 a = g[0], b = g[1];
        vd[r][0] = pack2(a.x, a.x);
        vd[r][1] = pack2(a.y, a.y);
        vd[r][2] = pack2(a.z, a.z);
        vd[r][3] = pack2(a.w, a.w);
        vd[r][4] = pack2(b.x, b.x);
        vd[r][5] = pack2(b.y, b.y);
        vd[r][6] = pack2(b.z, b.z);
        vd[r][7] = pack2(b.w, b.w);
    }

    float gbest[ROWS_PER_T] = {FLT_MAX, FLT_MAX, FLT_MAX, FLT_MAX};
    int   cid  [ROWS_PER_T] = {0, 0, 0, 0};

    // ---- pass 1: chunk-min scan. Inner loop has ZERO FSETP/SEL.
    //      Inner s-loop is unroll 2 (NOT full): full unroll makes ptxas
    //      hoist 8 steps of LDS results (~144 regs) and demote vd to
    //      local memory (R6/R7 regression, L1=85%). ----
#pragma unroll 1
    for (int c = 0; c < NCHUNK; c++) {
        float cm[ROWS_PER_T];
#pragma unroll
        for (int r = 0; r < ROWS_PER_T; r++) cm[r] = FLT_MAX;

        const u64* chunk = s_pair[c * SPC];
#pragma unroll 2
        for (int s = 0; s < SPC; s++) {
            const u64* rec = chunk + s * PAIR_STRIDE;
            const ulonglong2* rp = reinterpret_cast<const ulonglong2*>(rec);
            ulonglong2 q0 = rp[0];
            ulonglong2 q1 = rp[1];
            ulonglong2 q2 = rp[2];
            ulonglong2 q3 = rp[3];
            u64 c2p = rec[8];

#pragma unroll
            for (int r = 0; r < ROWS_PER_T; r++) {
                u64 acc = score_pair(c2p, q0, q1, q2, q3, vd[r]);
                float sa, sb;
                unpack2(acc, sa, sb);
                // tree min: only loop-carried dep is one 4-cycle FMNMX
                cm[r] = fminf(cm[r], fminf(sa, sb));
            }
        }

        // chunk boundary: amortized bookkeeping (1 FSETP+SEL per row per 8 steps)
#pragma unroll
        for (int r = 0; r < ROWS_PER_T; r++) {
            // strict '<': earliest chunk wins exact ties
            if (cm[r] < gbest[r]) cid[r] = c;
            gbest[r] = fminf(gbest[r], cm[r]);
        }
    }

    // ---- pass 2: recover exact index inside winning chunk (bit-exact).
    //      r-loop fully unrolled (static vd indexing); s-loop rolled
    //      (dynamic indexing touches smem only). ----
    int idx[ROWS_PER_T];
#pragma unroll
    for (int r = 0; r < ROWS_PER_T; r++) {
        const int base = cid[r] * SPC;
        int found = -1;
#pragma unroll 1
        for (int s = 0; s < SPC; s++) {
            const u64* rec = s_pair[base + s];
            const ulonglong2* rp = reinterpret_cast<const ulonglong2*>(rec);
            u64 acc = score_pair(rec[8], rp[0], rp[1], rp[2], rp[3], vd[r]);
            float sa, sb;
            unpack2(acc, sa, sb);
            // ascending scan, sa (even k) checked first => lowest k on ties
            if (found < 0) {
                if (sa == gbest[r])      found = 2 * (base + s);
                else if (sb == gbest[r]) found = 2 * (base + s) + 1;
            }
        }
        idx[r] = (found < 0) ? 0 : found;   // found>=0 always; safety
    }

    // ---- epilogue: gather winning code; c = (-2c) * -0.5 is bit-exact ----
#pragma unroll
    for (int r = 0; r < ROWS_PER_T; r++) {
        int k = idx[r];
        const float* h = reinterpret_cast<const float*>(s_pair[k >> 1]) + (k & 1);
        float4 oa, ob;
        oa.x = -0.5f * h[0];
        oa.y = -0.5f * h[2];
        oa.z = -0.5f * h[4];
        oa.w = -0.5f * h[6];
        ob.x = -0.5f * h[8];
        ob.y = -0.5f * h[10];
        ob.z = -0.5f * h[12];
        ob.w = -0.5f * h[14];
        float4* o = reinterpret_cast<float4*>(out + (size_t)rows[r] * EMB + p * ND);
        o[0] = oa;
        o[1] = ob;
    }
}

extern "C" void kernel_launch(void* const* d_in, const int* in_sizes, int n_in,
                              void* d_out, int out_size) {
    const float* vecs     = (const float*)d_in[0];   // [8192, 768] f32
    const float* codebook = (const float*)d_in[1];   // [96, 256, 8] f32
    float* out            = (float*)d_out;           // [8192, 768] f32

    dim3 grid(GRID_X, NP);
    dim3 block(THREADS);
    pq_argmin_kernel<<<grid, block>>>(vecs, codebook, out);
}

// round 9
// speedup vs baseline: 1.7283x; 1.7283x over previous
#include <cuda_runtime.h>
#include <cstdint>
#include <cfloat>

// Problem constants (fixed by the reference)
#define NB   8192
#define EMB  768
#define NP   96
#define NK   256
#define ND   8
#define NKP  (NK / 2)        // 128 k-pair steps
#define NGRP (NKP / 2)       // 64 groups of 2 steps = 4 codes

#define THREADS      128
#define ROWS_PER_T   4
#define ROWS_PER_BLK (THREADS * ROWS_PER_T)   // 512
#define GRID_X       (NB / ROWS_PER_BLK)      // 16

#define PAIR_STRIDE  10      // u64 per k-pair record (8 dims + c2 + pad)

typedef unsigned long long u64;

__device__ __forceinline__ u64 ffma2(u64 a, u64 b, u64 c) {
    u64 d;
    asm("fma.rn.f32x2 %0, %1, %2, %3;" : "=l"(d) : "l"(a), "l"(b), "l"(c));
    return d;
}
__device__ __forceinline__ u64 pack2(float lo, float hi) {
    u64 r;
    asm("mov.b64 %0, {%1, %2};" : "=l"(r) : "f"(lo), "f"(hi));
    return r;
}
__device__ __forceinline__ void unpack2(u64 v, float& lo, float& hi) {
    asm("mov.b64 {%0, %1}, %2;" : "=f"(lo), "=f"(hi) : "l"(v));
}

// Exact score chain — serially dependent, so recomputation is bit-identical.
__device__ __forceinline__ u64 score_pair(u64 c2, ulonglong2 q0, ulonglong2 q1,
                                          ulonglong2 q2, ulonglong2 q3,
                                          const u64* vd) {
    u64 acc = c2;
    acc = ffma2(vd[0], q0.x, acc);
    acc = ffma2(vd[1], q0.y, acc);
    acc = ffma2(vd[2], q1.x, acc);
    acc = ffma2(vd[3], q1.y, acc);
    acc = ffma2(vd[4], q2.x, acc);
    acc = ffma2(vd[5], q2.y, acc);
    acc = ffma2(vd[6], q3.x, acc);
    acc = ffma2(vd[7], q3.y, acc);
    return acc;
}

__global__ __launch_bounds__(THREADS, 5)
void pq_argmin_kernel(const float* __restrict__ vecs,
                      const float* __restrict__ codebook,
                      float* __restrict__ out) {
    // Per k-pair record: d0..d7 packed as (-2*c_{2s,d}, -2*c_{2s+1,d}),
    // then (||c_2s||^2, ||c_2s+1||^2). Stride 10 u64 = 80B.
    __shared__ __align__(16) u64 s_pair[NKP][PAIR_STRIDE];  // 10 KB

    const int p   = blockIdx.y;
    const int tid = threadIdx.x;

    // ---- stage codebook[p] into smem: one k-pair per thread ----
    {
        const int kp = tid;  // THREADS == NKP
        const float4* cb = reinterpret_cast<const float4*>(
            codebook + ((size_t)p * NK + 2 * kp) * ND);
        float4 a0 = cb[0], a1 = cb[1];   // code 2kp
        float4 b0 = cb[2], b1 = cb[3];   // code 2kp+1
        float c2a = a0.x*a0.x + a0.y*a0.y + a0.z*a0.z + a0.w*a0.w
                  + a1.x*a1.x + a1.y*a1.y + a1.z*a1.z + a1.w*a1.w;
        float c2b = b0.x*b0.x + b0.y*b0.y + b0.z*b0.z + b0.w*b0.w
                  + b1.x*b1.x + b1.y*b1.y + b1.z*b1.z + b1.w*b1.w;
        u64* rec = s_pair[kp];
        rec[0] = pack2(-2.f*a0.x, -2.f*b0.x);
        rec[1] = pack2(-2.f*a0.y, -2.f*b0.y);
        rec[2] = pack2(-2.f*a0.z, -2.f*b0.z);
        rec[3] = pack2(-2.f*a0.w, -2.f*b0.w);
        rec[4] = pack2(-2.f*a1.x, -2.f*b1.x);
        rec[5] = pack2(-2.f*a1.y, -2.f*b1.y);
        rec[6] = pack2(-2.f*a1.z, -2.f*b1.z);
        rec[7] = pack2(-2.f*a1.w, -2.f*b1.w);
        rec[8] = pack2(c2a, c2b);
    }
    __syncthreads();

    // ---- load 4 rows' v-slices (each slice is one 32B sector) ----
    const int rowBase = blockIdx.x * ROWS_PER_BLK;
    int rows[ROWS_PER_T];
    rows[0] = rowBase + tid;
    rows[1] = rows[0] + THREADS;
    rows[2] = rows[0] + 2 * THREADS;
    rows[3] = rows[0] + 3 * THREADS;

    // v duplicated into both f32x2 lanes, per row per dim.
    // vd is only ever indexed by compile-time constants.
    u64 vd[ROWS_PER_T][ND];
#pragma unroll
    for (int r = 0; r < ROWS_PER_T; r++) {
        const float4* g = reinterpret_cast<const float4*>(
            vecs + (size_t)rows[r] * EMB + p * ND);
        float4 a = g[0], b = g[1];
        vd[r][0] = pack2(a.x, a.x);
        vd[r][1] = pack2(a.y, a.y);
        vd[r][2] = pack2(a.z, a.z);
        vd[r][3] = pack2(a.w, a.w);
        vd[r][4] = pack2(b.x, b.x);
        vd[r][5] = pack2(b.y, b.y);
        vd[r][6] = pack2(b.z, b.z);
        vd[r][7] = pack2(b.w, b.w);
    }

    float best [ROWS_PER_T] = {FLT_MAX, FLT_MAX, FLT_MAX, FLT_MAX};
    int   bestG[ROWS_PER_T] = {0, 0, 0, 0};

    // ---- main loop: 64 groups of 2 pair-steps (4 codes each).
    //      Same single-loop shape as the proven 82us kernel; the argmin
    //      bookkeeping (FSETP/SEL) runs once per GROUP, not per step. ----
#pragma unroll 1
    for (int g = 0; g < NGRP; g++) {
        const u64* rec0 = s_pair[2 * g];
        const u64* rec1 = s_pair[2 * g + 1];

        // step A (codes 4g, 4g+1)
        const ulonglong2* rp0 = reinterpret_cast<const ulonglong2*>(rec0);
        ulonglong2 a0 = rp0[0];
        ulonglong2 a1 = rp0[1];
        ulonglong2 a2 = rp0[2];
        ulonglong2 a3 = rp0[3];
        u64 ac2 = rec0[8];

        float m0[ROWS_PER_T];
#pragma unroll
        for (int r = 0; r < ROWS_PER_T; r++) {
            u64 acc = score_pair(ac2, a0, a1, a2, a3, vd[r]);
            float sa, sb;
            unpack2(acc, sa, sb);
            m0[r] = fminf(sa, sb);
        }

        // step B (codes 4g+2, 4g+3)
        const ulonglong2* rp1 = reinterpret_cast<const ulonglong2*>(rec1);
        ulonglong2 b0 = rp1[0];
        ulonglong2 b1 = rp1[1];
        ulonglong2 b2 = rp1[2];
        ulonglong2 b3 = rp1[3];
        u64 bc2 = rec1[8];

#pragma unroll
        for (int r = 0; r < ROWS_PER_T; r++) {
            u64 acc = score_pair(bc2, b0, b1, b2, b3, vd[r]);
            float sa, sb;
            unpack2(acc, sa, sb);
            float m = fminf(m0[r], fminf(sa, sb));
            // strict '<': earliest group wins exact ties
            if (m < best[r]) bestG[r] = g;
            best[r] = fminf(best[r], m);
        }
    }

    // ---- resolve exact index inside winning group (bit-exact recompute).
    //      r-loop fully unrolled (static vd indexing); dynamic indexing
    //      below touches shared memory only. ----
    int idx[ROWS_PER_T];
#pragma unroll
    for (int r = 0; r < ROWS_PER_T; r++) {
        const int s0 = 2 * bestG[r];
        const u64* rec0 = s_pair[s0];
        const u64* rec1 = s_pair[s0 + 1];
        const ulonglong2* rp0 = reinterpret_cast<const ulonglong2*>(rec0);
        const ulonglong2* rp1 = reinterpret_cast<const ulonglong2*>(rec1);
        u64 accA = score_pair(rec0[8], rp0[0], rp0[1], rp0[2], rp0[3], vd[r]);
        u64 accB = score_pair(rec1[8], rp1[0], rp1[1], rp1[2], rp1[3], vd[r]);
        float sa0, sb0, sa1, sb1;
        unpack2(accA, sa0, sb0);
        unpack2(accB, sa1, sb1);
        // ascending scan => lowest k wins exact ties (jnp.argmax semantics)
        int k = 2 * s0 + 3;
        if (sa1 == best[r]) k = 2 * s0 + 2;
        if (sb0 == best[r]) k = 2 * s0 + 1;
        if (sa0 == best[r]) k = 2 * s0;
        idx[r] = k;
    }

    // ---- epilogue: gather winning code; c = (-2c) * -0.5 is bit-exact ----
#pragma unroll
    for (int r = 0; r < ROWS_PER_T; r++) {
        int k = idx[r];
        const float* h = reinterpret_cast<const float*>(s_pair[k >> 1]) + (k & 1);
        float4 oa, ob;
        oa.x = -0.5f * h[0];
        oa.y = -0.5f * h[2];
        oa.z = -0.5f * h[4];
        oa.w = -0.5f * h[6];
        ob.x = -0.5f * h[8];
        ob.y = -0.5f * h[10];
        ob.z = -0.5f * h[12];
        ob.w = -0.5f * h[14];
        float4* o = reinterpret_cast<float4*>(out + (size_t)rows[r] * EMB + p * ND);
        o[0] = oa;
        o[1] = ob;
    }
}

extern "C" void kernel_launch(void* const* d_in, const int* in_sizes, int n_in,
                              void* d_out, int out_size) {
    const float* vecs     = (const float*)d_in[0];   // [8192, 768] f32
    const float* codebook = (const float*)d_in[1];   // [96, 256, 8] f32
    float* out            = (float*)d_out;           // [8192, 768] f32

    dim3 grid(GRID_X, NP);
    dim3 block(THREADS);
    pq_argmin_kernel<<<grid, block>>>(vecs, codebook, out);
}

// round 10
// speedup vs baseline: 1.7580x; 1.0172x over previous
#include <cuda_runtime.h>
#include <cstdint>
#include <cfloat>

// Problem constants (fixed by the reference)
#define NB   8192
#define EMB  768
#define NP   96
#define NK   256
#define ND   8
#define NKP  (NK / 2)        // 128 k-pair steps
#define NGRP (NKP / 2)       // 64 groups of 2 steps = 4 codes

#define THREADS      128
#define ROWS_PER_T   4
#define ROWS_PER_BLK (THREADS * ROWS_PER_T)   // 512
#define GRID_X       (NB / ROWS_PER_BLK)      // 16

#define PAIR_STRIDE  10      // u64 per k-pair record (8 dims + c2 + pad)

typedef unsigned long long u64;

__device__ __forceinline__ u64 ffma2(u64 a, u64 b, u64 c) {
    u64 d;
    asm("fma.rn.f32x2 %0, %1, %2, %3;" : "=l"(d) : "l"(a), "l"(b), "l"(c));
    return d;
}
__device__ __forceinline__ u64 pack2(float lo, float hi) {
    u64 r;
    asm("mov.b64 %0, {%1, %2};" : "=l"(r) : "f"(lo), "f"(hi));
    return r;
}
__device__ __forceinline__ void unpack2(u64 v, float& lo, float& hi) {
    asm("mov.b64 {%0, %1}, %2;" : "=f"(lo), "=f"(hi) : "l"(v));
}

// Exact score chain — serially dependent, so recomputation is bit-identical.
__device__ __forceinline__ u64 score_pair(u64 c2, ulonglong2 q0, ulonglong2 q1,
                                          ulonglong2 q2, ulonglong2 q3,
                                          const u64* vd) {
    u64 acc = c2;
    acc = ffma2(vd[0], q0.x, acc);
    acc = ffma2(vd[1], q0.y, acc);
    acc = ffma2(vd[2], q1.x, acc);
    acc = ffma2(vd[3], q1.y, acc);
    acc = ffma2(vd[4], q2.x, acc);
    acc = ffma2(vd[5], q2.y, acc);
    acc = ffma2(vd[6], q3.x, acc);
    acc = ffma2(vd[7], q3.y, acc);
    return acc;
}

__global__ __launch_bounds__(THREADS, 6)
void pq_argmin_kernel(const float* __restrict__ vecs,
                      const float* __restrict__ codebook,
                      float* __restrict__ out) {
    // Per k-pair record: d0..d7 packed as (-2*c_{2s,d}, -2*c_{2s+1,d}),
    // then (||c_2s||^2, ||c_2s+1||^2). Stride 10 u64 = 80B.
    __shared__ __align__(16) u64 s_pair[NKP][PAIR_STRIDE];  // 10 KB

    const int p   = blockIdx.y;
    const int tid = threadIdx.x;

    // ---- stage codebook[p] into smem: one k-pair per thread ----
    {
        const int kp = tid;  // THREADS == NKP
        const float4* cb = reinterpret_cast<const float4*>(
            codebook + ((size_t)p * NK + 2 * kp) * ND);
        float4 a0 = cb[0], a1 = cb[1];   // code 2kp
        float4 b0 = cb[2], b1 = cb[3];   // code 2kp+1
        float c2a = a0.x*a0.x + a0.y*a0.y + a0.z*a0.z + a0.w*a0.w
                  + a1.x*a1.x + a1.y*a1.y + a1.z*a1.z + a1.w*a1.w;
        float c2b = b0.x*b0.x + b0.y*b0.y + b0.z*b0.z + b0.w*b0.w
                  + b1.x*b1.x + b1.y*b1.y + b1.z*b1.z + b1.w*b1.w;
        u64* rec = s_pair[kp];
        rec[0] = pack2(-2.f*a0.x, -2.f*b0.x);
        rec[1] = pack2(-2.f*a0.y, -2.f*b0.y);
        rec[2] = pack2(-2.f*a0.z, -2.f*b0.z);
        rec[3] = pack2(-2.f*a0.w, -2.f*b0.w);
        rec[4] = pack2(-2.f*a1.x, -2.f*b1.x);
        rec[5] = pack2(-2.f*a1.y, -2.f*b1.y);
        rec[6] = pack2(-2.f*a1.z, -2.f*b1.z);
        rec[7] = pack2(-2.f*a1.w, -2.f*b1.w);
        rec[8] = pack2(c2a, c2b);
    }
    __syncthreads();

    // ---- load 4 rows' v-slices via ONE base pointer + immediate offsets ----
    const float* vbase =
        vecs + (size_t)(blockIdx.x * ROWS_PER_BLK + tid) * EMB + p * ND;

    // v duplicated into both f32x2 lanes, per row per dim.
    // vd is only ever indexed by compile-time constants.
    u64 vd[ROWS_PER_T][ND];
#pragma unroll
    for (int r = 0; r < ROWS_PER_T; r++) {
        const float4* g = reinterpret_cast<const float4*>(
            vbase + (size_t)r * THREADS * EMB);
        float4 a = g[0], b = g[1];
        vd[r][0] = pack2(a.x, a.x);
        vd[r][1] = pack2(a.y, a.y);
        vd[r][2] = pack2(a.z, a.z);
        vd[r][3] = pack2(a.w, a.w);
        vd[r][4] = pack2(b.x, b.x);
        vd[r][5] = pack2(b.y, b.y);
        vd[r][6] = pack2(b.z, b.z);
        vd[r][7] = pack2(b.w, b.w);
    }

    float best [ROWS_PER_T] = {FLT_MAX, FLT_MAX, FLT_MAX, FLT_MAX};
    int   bestG[ROWS_PER_T] = {0, 0, 0, 0};

    // ---- main loop: 64 groups of 2 pair-steps (4 codes each).
    //      Argmin bookkeeping (FSETP/SEL) runs once per GROUP. ----
#pragma unroll 1
    for (int g = 0; g < NGRP; g++) {
        const u64* rec0 = s_pair[2 * g];
        const u64* rec1 = s_pair[2 * g + 1];

        // step A (codes 4g, 4g+1)
        const ulonglong2* rp0 = reinterpret_cast<const ulonglong2*>(rec0);
        ulonglong2 a0 = rp0[0];
        ulonglong2 a1 = rp0[1];
        ulonglong2 a2 = rp0[2];
        ulonglong2 a3 = rp0[3];
        u64 ac2 = rec0[8];

        float m0[ROWS_PER_T];
#pragma unroll
        for (int r = 0; r < ROWS_PER_T; r++) {
            u64 acc = score_pair(ac2, a0, a1, a2, a3, vd[r]);
            float sa, sb;
            unpack2(acc, sa, sb);
            m0[r] = fminf(sa, sb);
        }

        // step B (codes 4g+2, 4g+3)
        const ulonglong2* rp1 = reinterpret_cast<const ulonglong2*>(rec1);
        ulonglong2 b0 = rp1[0];
        ulonglong2 b1 = rp1[1];
        ulonglong2 b2 = rp1[2];
        ulonglong2 b3 = rp1[3];
        u64 bc2 = rec1[8];

#pragma unroll
        for (int r = 0; r < ROWS_PER_T; r++) {
            u64 acc = score_pair(bc2, b0, b1, b2, b3, vd[r]);
            float sa, sb;
            unpack2(acc, sa, sb);
            float m = fminf(m0[r], fminf(sa, sb));
            // strict '<': earliest group wins exact ties
            if (m < best[r]) bestG[r] = g;
            best[r] = fminf(best[r], m);
        }
    }

    // ---- fused: resolve index inside winning group (bit-exact recompute)
    //      + gather + store, one row at a time (minimizes live state).
    //      r-loop fully unrolled (static vd indexing); dynamic indexing
    //      below touches shared memory only. ----
    float* obase =
        out + (size_t)(blockIdx.x * ROWS_PER_BLK + tid) * EMB + p * ND;
#pragma unroll
    for (int r = 0; r < ROWS_PER_T; r++) {
        const int s0 = 2 * bestG[r];
        const u64* rec0 = s_pair[s0];
        const u64* rec1 = s_pair[s0 + 1];
        const ulonglong2* rp0 = reinterpret_cast<const ulonglong2*>(rec0);
        const ulonglong2* rp1 = reinterpret_cast<const ulonglong2*>(rec1);
        u64 accA = score_pair(rec0[8], rp0[0], rp0[1], rp0[2], rp0[3], vd[r]);
        u64 accB = score_pair(rec1[8], rp1[0], rp1[1], rp1[2], rp1[3], vd[r]);
        float sa0, sb0, sa1, sb1;
        unpack2(accA, sa0, sb0);
        unpack2(accB, sa1, sb1);
        // ascending priority => lowest k wins exact ties (jnp.argmax semantics)
        int k = 2 * s0 + 3;
        if (sa1 == best[r]) k = 2 * s0 + 2;
        if (sb0 == best[r]) k = 2 * s0 + 1;
        if (sa0 == best[r]) k = 2 * s0;

        // gather winning code; c = (-2c) * -0.5 is bit-exact
        const float* h = reinterpret_cast<const float*>(s_pair[k >> 1]) + (k & 1);
        float4 oa, ob;
        oa.x = -0.5f * h[0];
        oa.y = -0.5f * h[2];
        oa.z = -0.5f * h[4];
        oa.w = -0.5f * h[6];
        ob.x = -0.5f * h[8];
        ob.y = -0.5f * h[10];
        ob.z = -0.5f * h[12];
        ob.w = -0.5f * h[14];
        float4* o = reinterpret_cast<float4*>(obase + (size_t)r * THREADS * EMB);
        o[0] = oa;
        o[1] = ob;
    }
}

extern "C" void kernel_launch(void* const* d_in, const int* in_sizes, int n_in,
                              void* d_out, int out_size) {
    const float* vecs     = (const float*)d_in[0];   // [8192, 768] f32
    const float* codebook = (const float*)d_in[1];   // [96, 256, 8] f32
    float* out            = (float*)d_out;           // [8192, 768] f32

    dim3 grid(GRID_X, NP);
    dim3 block(THREADS);
    pq_argmin_kernel<<<grid, block>>>(vecs, codebook, out);
}